// round 9
// baseline (speedup 1.0000x reference)
#include <cuda_runtime.h>
#include <cuda_bf16.h>
#include <cstdint>
#include <math_constants.h>

// MiniRocket via mma.sync (HMMA) bf16 split GEMM, round 9.
// R9: 3-stage cp.async ring (issue distance 2 chunks), ONE syncthreads per
// chunk (cutlass multistage pattern). Warp tile 32j x 32t, K=224 (hi|lo,
// same W reused), 4 CTAs/SM.

#define LSEQ    5000
#define PADX    2112
#define ROWLEN  9224            // PADX + LSEQ + PADX
#define NCH     12
#define NROWS   192             // 16 batch * 12 ch
#define NCHUNK  157             // ceil(5000/32)
#define ASTRIDE 240             // A row stride bytes (112 bf16 + pad), 16 | 240

#define BSZ     14336           // 14 atoms x 1024B per stage
#define NSTAGE  3
#define SMEMSZ  (NSTAGE * BSZ)  // 43008; A staging (30720) overlaid on stages

typedef unsigned u32;

// merged hi/lo, 8 shifts: g_x8[((part*8)+s)*NROWS + row][p] ; part 0=hi, 1=lo
__device__ __align__(16) __nv_bfloat16 g_x8[16 * NROWS * ROWLEN];

// ---------------- prep: padded, hi/lo split, 8 shifts ----------------
__global__ void prep_kernel(const float* __restrict__ x) {
    int p2 = blockIdx.x * 256 + threadIdx.x;
    if (p2 >= ROWLEN / 2) return;
    int row = blockIdx.y;                      // 0..191
    int s   = blockIdx.z;                      // 0..7
    int p   = p2 * 2;

    float v0 = 0.f, v1 = 0.f;
    int i0 = p + s - PADX, i1 = i0 + 1;
    if (i0 >= 0 && i0 < LSEQ) v0 = x[(size_t)row * LSEQ + i0];
    if (i1 >= 0 && i1 < LSEQ) v1 = x[(size_t)row * LSEQ + i1];

    __nv_bfloat16 h0 = __float2bfloat16(v0);
    __nv_bfloat16 h1 = __float2bfloat16(v1);
    __nv_bfloat16 l0 = __float2bfloat16(v0 - __bfloat162float(h0));
    __nv_bfloat16 l1 = __float2bfloat16(v1 - __bfloat162float(h1));

    size_t oh = ((size_t)s * NROWS + row) * ROWLEN + p;
    size_t ol = ((size_t)(8 + s) * NROWS + row) * ROWLEN + p;
    __nv_bfloat162 hh; hh.x = h0; hh.y = h1;
    __nv_bfloat162 ll; ll.x = l0; ll.y = l1;
    *reinterpret_cast<__nv_bfloat162*>(g_x8 + oh) = hh;
    *reinterpret_cast<__nv_bfloat162*>(g_x8 + ol) = ll;
}

// ---------------- PTX helpers (baseline, sm_80+) ----------------
__device__ __forceinline__ u32 smem_u32(const void* p) {
    u32 a;
    asm("{ .reg .u64 t; cvta.to.shared.u64 t, %1; cvt.u32.u64 %0, t; }"
        : "=r"(a) : "l"(p));
    return a;
}
__device__ __forceinline__ void ldsm_x4(u32& r0, u32& r1, u32& r2, u32& r3, u32 a) {
    asm volatile("ldmatrix.sync.aligned.m8n8.x4.shared.b16 {%0,%1,%2,%3}, [%4];"
                 : "=r"(r0), "=r"(r1), "=r"(r2), "=r"(r3) : "r"(a));
}
__device__ __forceinline__ void ldsm_x4t(u32& r0, u32& r1, u32& r2, u32& r3, u32 a) {
    asm volatile("ldmatrix.sync.aligned.m8n8.x4.trans.shared.b16 {%0,%1,%2,%3}, [%4];"
                 : "=r"(r0), "=r"(r1), "=r"(r2), "=r"(r3) : "r"(a));
}
__device__ __forceinline__ void mma16816(float* d, const u32* a, u32 b0, u32 b1) {
    asm volatile(
        "mma.sync.aligned.m16n8k16.row.col.f32.bf16.bf16.f32 "
        "{%0,%1,%2,%3}, {%4,%5,%6,%7}, {%8,%9}, {%0,%1,%2,%3};"
        : "+f"(d[0]), "+f"(d[1]), "+f"(d[2]), "+f"(d[3])
        : "r"(a[0]), "r"(a[1]), "r"(a[2]), "r"(a[3]), "r"(b0), "r"(b1));
}
__device__ __forceinline__ void cp16(u32 dst, const void* src) {
    asm volatile("cp.async.cg.shared.global [%0], [%1], 16;"
                 :: "r"(dst), "l"(src) : "memory");
}
#define CP_COMMIT() asm volatile("cp.async.commit_group;" ::: "memory")
#define CP_WAIT(n)  asm volatile("cp.async.wait_group %0;" :: "n"(n) : "memory")

// ---------------- main kernel ----------------
__global__ void __launch_bounds__(128, 4)
mr_hmma(const float* __restrict__ W, const float* __restrict__ bias,
        float* __restrict__ out)
{
    extern __shared__ __align__(1024) char smem[];
    const u32 sb = smem_u32(smem);
    const int tid  = threadIdx.x;
    const int wid  = tid >> 5;      // 0..3
    const int lane = tid & 31;

    const int jt = blockIdx.x;      // 0..7
    const int b  = blockIdx.y;      // 0..15
    const int di = blockIdx.z;      // 0..9
    const int d  = 1 << di;

    // ---- stage A [128 j x 112 K] bf16 (overlaid on stages; used once) ----
    for (int e = tid; e < 128 * 56; e += 128) {
        int j  = e / 56;
        int kk = (e - j * 56) * 2;
        u32 val = 0;
        int jg = jt * 128 + j;
        if (jg < 1000 && kk < 108) {
            float2 w2 = *reinterpret_cast<const float2*>(
                W + (size_t)(di * 1000 + jg) * 108 + kk);
            __nv_bfloat162 h = __floats2bfloat162_rn(w2.x, w2.y);
            val = *reinterpret_cast<u32*>(&h);
        }
        *reinterpret_cast<u32*>(smem + j * ASTRIDE + kk * 2) = val;
    }
    __syncthreads();

    // ---- A fragments: 7 ksteps x 2 mtiles x 4 regs ----
    u32 afr[7][2][4];
#pragma unroll
    for (int mt = 0; mt < 2; mt++) {
        u32 abase = sb + (u32)(wid * 32 + mt * 16 + (lane & 15)) * ASTRIDE
                  + (u32)(lane >> 4) * 16;
#pragma unroll
        for (int q = 0; q < 7; q++)
            ldsm_x4(afr[q][mt][0], afr[q][mt][1], afr[q][mt][2], afr[q][mt][3],
                    abase + q * 32);
    }
    __syncthreads();   // frags loaded before stage buffers are written

    // ---- staging descriptors: 7 slots/thread (864 valid of 896) ----
    // smem row r2 (0..107 real, 108..111 pad): hi in bytes 0..63, lo 64..127.
    u32 so[7];  // element offset into g_x8 (advanced by 32 per chunk)
    u32 sd[7];  // swizzled smem byte offset (~0 = invalid)
#pragma unroll
    for (int sx = 0; sx < 7; sx++) {
        int e = tid + (sx << 7);
        bool valid = e < 216 * 4;
        int row = valid ? (e >> 2) : 0;
        int ch  = e & 3;
        bool ishi = row < 108;
        int r2 = ishi ? row : row - 108;
        int c = r2 / 9, k = r2 - c * 9;
        int o0 = PADX + (k - 4) * d + ch * 8;
        int s8 = o0 & 7, p0 = o0 - s8;
        so[sx] = (u32)((((ishi ? 0 : 8) + s8) * NROWS + b * NCH + c) * ROWLEN + p0);
        int rb = r2 & 7;
        u32 off = (u32)(r2 >> 3) * 1024u + (u32)rb * 128u
                + ((u32)(((ishi ? 0 : 4) + ch) ^ rb) * 16u);
        sd[sx] = valid ? off : 0xFFFFFFFFu;
    }

    // ---- zero pad rows 108..111 of all 3 stages ----
    if (tid < 96) {
        int st = tid >> 5, q = tid & 31;
        int rr = 108 + (q >> 3), c8 = q & 7;
        u32 off = (u32)(rr >> 3) * 1024u + (u32)(rr & 7) * 128u
                + ((u32)(c8 ^ (rr & 7)) * 16u);
        *reinterpret_cast<uint4*>(smem + st * BSZ + off) = make_uint4(0, 0, 0, 0);
    }

    // ---- prologue: async-stage chunks 0 and 1 (separate groups) ----
    const __nv_bfloat16* gx = g_x8;
#pragma unroll
    for (int sx = 0; sx < 7; sx++)
        if (sd[sx] != 0xFFFFFFFFu) cp16(sb + 0 * BSZ + sd[sx], gx + so[sx]);
    CP_COMMIT();
#pragma unroll
    for (int sx = 0; sx < 7; sx++)
        if (sd[sx] != 0xFFFFFFFFu) cp16(sb + 1 * BSZ + sd[sx], gx + so[sx] + 32u);
    CP_COMMIT();

    // ---- per-lane ldsm-B address components ----
    const u32 rb7  = lane & 7;
    const u32 hi8  = (u32)((lane & 15) >> 3);
    const u32 g0   = (u32)(lane >> 4);
    const u32 laneBase = hi8 * 1024u + rb7 * 128u;
    u32 xv[2][2];
#pragma unroll
    for (int h = 0; h < 2; h++)
#pragma unroll
        for (int p = 0; p < 2; p++)
            xv[h][p] = (((u32)(h * 4) + g0 + (u32)(2 * p)) ^ rb7) * 16u;

    // ---- epilogue state: lane owns 4 j rows ----
    const int qd  = lane >> 2;
    const int j0w = jt * 128 + wid * 32;
    int jr[4] = { j0w + qd, j0w + qd + 8, j0w + 16 + qd, j0w + 24 + qd };
    float bv[4], m[4];
    int   cn[4];
#pragma unroll
    for (int r = 0; r < 4; r++) {
        bv[r] = (jr[r] < 1000) ? bias[di * 1000 + jr[r]] : 0.0f;
        m[r]  = -CUDART_INF_F;
        cn[r] = 0;
    }

    int cur = 0;          // stage holding chunk i
    int wr  = 2;          // stage to write chunk i+2 into ( = (cur+2)%3 )
    u32 eoff = 64;        // element offset of chunk i+2

    for (int i = 0; i < NCHUNK; i++) {
        CP_WAIT(1);            // chunk i resident (issued 2 iterations ago)
        __syncthreads();       // visible to all warps; stage 'wr' fully drained

        // issue chunk i+2 into stage wr (empty commit at tail keeps counts)
        if (i + 2 < NCHUNK) {
            const u32 bw = sb + (u32)wr * BSZ;
#pragma unroll
            for (int sx = 0; sx < 7; sx++)
                if (sd[sx] != 0xFFFFFFFFu)
                    cp16(bw + sd[sx], gx + so[sx] + eoff);
        }
        CP_COMMIT();
        eoff += 32;

        // MMA chunk i: D[32j x 32t] per warp
        float dacc[2][4][4];
#pragma unroll
        for (int mt = 0; mt < 2; mt++)
#pragma unroll
            for (int n = 0; n < 4; n++)
#pragma unroll
                for (int r = 0; r < 4; r++) dacc[mt][n][r] = 0.f;

        const u32 bb = sb + (u32)cur * BSZ + laneBase;
#pragma unroll
        for (int q = 0; q < 14; q++) {
            const int q7 = (q < 7) ? q : q - 7;
            const int h  = (q < 7) ? 0 : 1;
#pragma unroll
            for (int p = 0; p < 2; p++) {
                u32 b0, b1, b2, b3;
                ldsm_x4t(b0, b1, b2, b3, bb + (u32)q7 * 2048u + xv[h][p]);
                mma16816(dacc[0][2 * p],     afr[q7][0], b0, b1);
                mma16816(dacc[0][2 * p + 1], afr[q7][0], b2, b3);
                mma16816(dacc[1][2 * p],     afr[q7][1], b0, b1);
                mma16816(dacc[1][2 * p + 1], afr[q7][1], b2, b3);
            }
        }

        // fused epilogue (last chunk: only t 0..7 valid -> ntile 0)
        const int ntmax = (i == NCHUNK - 1) ? 1 : 4;
#pragma unroll
        for (int n = 0; n < 4; n++) {
            if (n < ntmax) {
#pragma unroll
                for (int mt = 0; mt < 2; mt++) {
                    m[2 * mt]     = fmaxf(m[2 * mt],
                                          fmaxf(dacc[mt][n][0], dacc[mt][n][1]));
                    cn[2 * mt]   += (dacc[mt][n][0] > bv[2 * mt])
                                  + (dacc[mt][n][1] > bv[2 * mt]);
                    m[2 * mt + 1] = fmaxf(m[2 * mt + 1],
                                          fmaxf(dacc[mt][n][2], dacc[mt][n][3]));
                    cn[2 * mt + 1] += (dacc[mt][n][2] > bv[2 * mt + 1])
                                    + (dacc[mt][n][3] > bv[2 * mt + 1]);
                }
            }
        }

        cur = (cur == 2) ? 0 : cur + 1;
        wr  = (wr  == 2) ? 0 : wr  + 1;
    }

    // ---- reduce across the 4 lanes of each quad, write out ----
#pragma unroll
    for (int o = 1; o < 4; o <<= 1) {
#pragma unroll
        for (int r = 0; r < 4; r++) {
            m[r]  = fmaxf(m[r], __shfl_xor_sync(0xffffffffu, m[r], o));
            cn[r] += __shfl_xor_sync(0xffffffffu, cn[r], o);
        }
    }
    if ((lane & 3) == 0) {
        float* ob = out + (size_t)b * 20000 + di * 2000;
#pragma unroll
        for (int r = 0; r < 4; r++) {
            if (jr[r] < 1000) {
                ob[jr[r]]        = m[r];
                ob[1000 + jr[r]] = (float)cn[r] * (1.0f / LSEQ);
            }
        }
    }
}

extern "C" void kernel_launch(void* const* d_in, const int* in_sizes, int n_in,
                              void* d_out, int out_size)
{
    const float* x    = (const float*)d_in[0];  // [16,12,5000]
    const float* W    = (const float*)d_in[1];  // [10,1000,12,9]
    const float* bias = (const float*)d_in[2];  // [10,1000]
    float* out = (float*)d_out;                 // [16,20000]

    dim3 pg((ROWLEN / 2 + 255) / 256, NROWS, 8);
    prep_kernel<<<pg, 256>>>(x);

    cudaFuncSetAttribute(mr_hmma, cudaFuncAttributeMaxDynamicSharedMemorySize, SMEMSZ);
    dim3 grid(8, 16, 10);
    mr_hmma<<<grid, 128, SMEMSZ>>>(W, bias, out);
}

// round 10
// speedup vs baseline: 1.8269x; 1.8269x over previous
#include <cuda_runtime.h>
#include <cuda_fp16.h>
#include <cstdint>
#include <math_constants.h>

// MiniRocket via mma.sync (HMMA) fp16 single-precision GEMM, round 10.
// fp16 (11-bit mantissa) instead of bf16 hi/lo split -> K = 112 (one half),
// HALF the MMA instructions. Ternary W exact in fp16; expected norm rel err
// ~3e-4 < 1e-3. Warp tile 32j x 32t, 7 ksteps, 3-stage cp.async ring,
// 4 CTAs/SM. B layout: 56 rows x 128B, K-slot s at (row s>>1, half s&1),
// XOR swizzle on 16B chunks (conflict-free ldsm + cp.async).

#define LSEQ    5000
#define PADX    2112
#define ROWLEN  9224            // PADX + LSEQ + PADX
#define NCH     12
#define NROWS   192             // 16 batch * 12 ch
#define NCHUNK  157             // ceil(5000/32)
#define ASTRIDE 240             // A row stride bytes (112 fp16 + pad), 16 | 240

#define BSZ     7168            // 56 rows x 128B per stage
#define NSTAGE  3
#define SMEMSZ  30720           // A staging region (128*240) covers all stages

typedef unsigned u32;

// fp16 x, 8 shifted padded copies: g_xh[s*NROWS + row][p] = x[row][p + s - PADX]
__device__ __align__(16) __half g_xh[8 * NROWS * ROWLEN];

// ---------------- prep: padded fp16, 8 shifts ----------------
__global__ void prep_kernel(const float* __restrict__ x) {
    int p2 = blockIdx.x * 256 + threadIdx.x;
    if (p2 >= ROWLEN / 2) return;
    int row = blockIdx.y;                      // 0..191
    int s   = blockIdx.z;                      // 0..7
    int p   = p2 * 2;

    float v0 = 0.f, v1 = 0.f;
    int i0 = p + s - PADX, i1 = i0 + 1;
    if (i0 >= 0 && i0 < LSEQ) v0 = x[(size_t)row * LSEQ + i0];
    if (i1 >= 0 && i1 < LSEQ) v1 = x[(size_t)row * LSEQ + i1];

    __half2 h;
    h.x = __float2half(v0);
    h.y = __float2half(v1);
    *reinterpret_cast<__half2*>(g_xh + ((size_t)s * NROWS + row) * ROWLEN + p) = h;
}

// ---------------- PTX helpers (baseline, sm_80+) ----------------
__device__ __forceinline__ u32 smem_u32(const void* p) {
    u32 a;
    asm("{ .reg .u64 t; cvta.to.shared.u64 t, %1; cvt.u32.u64 %0, t; }"
        : "=r"(a) : "l"(p));
    return a;
}
__device__ __forceinline__ void ldsm_x4(u32& r0, u32& r1, u32& r2, u32& r3, u32 a) {
    asm volatile("ldmatrix.sync.aligned.m8n8.x4.shared.b16 {%0,%1,%2,%3}, [%4];"
                 : "=r"(r0), "=r"(r1), "=r"(r2), "=r"(r3) : "r"(a));
}
__device__ __forceinline__ void ldsm_x4t(u32& r0, u32& r1, u32& r2, u32& r3, u32 a) {
    asm volatile("ldmatrix.sync.aligned.m8n8.x4.trans.shared.b16 {%0,%1,%2,%3}, [%4];"
                 : "=r"(r0), "=r"(r1), "=r"(r2), "=r"(r3) : "r"(a));
}
__device__ __forceinline__ void mma16816(float* d, const u32* a, u32 b0, u32 b1) {
    asm volatile(
        "mma.sync.aligned.m16n8k16.row.col.f32.f16.f16.f32 "
        "{%0,%1,%2,%3}, {%4,%5,%6,%7}, {%8,%9}, {%0,%1,%2,%3};"
        : "+f"(d[0]), "+f"(d[1]), "+f"(d[2]), "+f"(d[3])
        : "r"(a[0]), "r"(a[1]), "r"(a[2]), "r"(a[3]), "r"(b0), "r"(b1));
}
__device__ __forceinline__ void cp16(u32 dst, const void* src) {
    asm volatile("cp.async.cg.shared.global [%0], [%1], 16;"
                 :: "r"(dst), "l"(src) : "memory");
}
#define CP_COMMIT() asm volatile("cp.async.commit_group;" ::: "memory")
#define CP_WAIT(n)  asm volatile("cp.async.wait_group %0;" :: "n"(n) : "memory")

// ---------------- main kernel ----------------
__global__ void __launch_bounds__(128, 4)
mr_hmma(const float* __restrict__ W, const float* __restrict__ bias,
        float* __restrict__ out)
{
    extern __shared__ __align__(1024) char smem[];
    const u32 sb = smem_u32(smem);
    const int tid  = threadIdx.x;
    const int wid  = tid >> 5;      // 0..3
    const int lane = tid & 31;

    const int jt = blockIdx.x;      // 0..7
    const int b  = blockIdx.y;      // 0..15
    const int di = blockIdx.z;      // 0..9
    const int d  = 1 << di;

    // ---- stage A [128 j x 112 K] fp16 (overlaid on stages; used once) ----
    for (int e = tid; e < 128 * 56; e += 128) {
        int j  = e / 56;
        int kk = (e - j * 56) * 2;
        u32 val = 0;
        int jg = jt * 128 + j;
        if (jg < 1000 && kk < 108) {
            float2 w2 = *reinterpret_cast<const float2*>(
                W + (size_t)(di * 1000 + jg) * 108 + kk);
            __half2 h;
            h.x = __float2half(w2.x);
            h.y = __float2half(w2.y);
            val = *reinterpret_cast<u32*>(&h);
        }
        *reinterpret_cast<u32*>(smem + j * ASTRIDE + kk * 2) = val;
    }
    __syncthreads();

    // ---- A fragments: 7 ksteps x 2 mtiles x 4 regs ----
    u32 afr[7][2][4];
#pragma unroll
    for (int mt = 0; mt < 2; mt++) {
        u32 abase = sb + (u32)(wid * 32 + mt * 16 + (lane & 15)) * ASTRIDE
                  + (u32)(lane >> 4) * 16;
#pragma unroll
        for (int q = 0; q < 7; q++)
            ldsm_x4(afr[q][mt][0], afr[q][mt][1], afr[q][mt][2], afr[q][mt][3],
                    abase + q * 32);
    }
    __syncthreads();   // frags loaded before stage buffers are written

    // ---- staging descriptors: 4 slots/thread (432 valid of 512) ----
    // K-slot s (0..107 real, 108..111 pad): smem row u = s>>1, half = s&1.
    // dst chunk = (half*4 + ch) ^ (u & 7);  ch = 16B t-chunk (0..3).
    u32 so[4];  // element offset into g_xh (advanced by 32 per chunk)
    u32 sd[4];  // swizzled smem byte offset (~0 = invalid)
#pragma unroll
    for (int sx = 0; sx < 4; sx++) {
        int e = tid + (sx << 7);
        bool valid = e < 108 * 4;
        int s  = valid ? (e >> 2) : 0;
        int ch = e & 3;
        int c = s / 9, k = s - c * 9;
        int o0 = PADX + (k - 4) * d + ch * 8;
        int s8 = o0 & 7, p0 = o0 - s8;
        so[sx] = (u32)((s8 * NROWS + b * NCH + c) * ROWLEN + p0);
        int u = s >> 1, half = s & 1;
        u32 off = (u32)u * 128u + ((u32)((half * 4 + ch) ^ (u & 7)) * 16u);
        sd[sx] = valid ? off : 0xFFFFFFFFu;
    }

    // ---- zero pad slots 108..111 in all 3 stages ----
    if (tid < 48) {
        int st = tid >> 4, idx = tid & 15;
        int s = 108 + (idx >> 2), ch = idx & 3;
        int u = s >> 1, half = s & 1;
        u32 off = (u32)u * 128u + ((u32)((half * 4 + ch) ^ (u & 7)) * 16u);
        *reinterpret_cast<uint4*>(smem + st * BSZ + off) = make_uint4(0, 0, 0, 0);
    }

    // ---- prologue: async-stage chunks 0 and 1 ----
    const __half* gx = g_xh;
#pragma unroll
    for (int sx = 0; sx < 4; sx++)
        if (sd[sx] != 0xFFFFFFFFu) cp16(sb + 0 * BSZ + sd[sx], gx + so[sx]);
    CP_COMMIT();
#pragma unroll
    for (int sx = 0; sx < 4; sx++)
        if (sd[sx] != 0xFFFFFFFFu) cp16(sb + 1 * BSZ + sd[sx], gx + so[sx] + 32u);
    CP_COMMIT();

    // ---- per-lane ldsm-B address components ----
    // lane l: K-slot s' = (l & 15) -> u-offset = s'>>1, half = s'&1;
    // g0 = l>>4 picks the t octet within the 16-t group p.
    const u32 laneU    = (u32)((lane & 15) >> 1);   // 0..7
    const u32 laneHalf = (u32)(lane & 1);
    const u32 g0       = (u32)(lane >> 4);
    const u32 laneBase = laneU * 128u;
    u32 xvo[2];
#pragma unroll
    for (int p = 0; p < 2; p++)
        xvo[p] = ((laneHalf * 4u + g0 + 2u * (u32)p) ^ laneU) * 16u;

    // ---- epilogue state: lane owns 4 j rows ----
    const int qd  = lane >> 2;
    const int j0w = jt * 128 + wid * 32;
    int jr[4] = { j0w + qd, j0w + qd + 8, j0w + 16 + qd, j0w + 24 + qd };
    float bv[4], m[4];
    int   cn[4];
#pragma unroll
    for (int r = 0; r < 4; r++) {
        bv[r] = (jr[r] < 1000) ? bias[di * 1000 + jr[r]] : 0.0f;
        m[r]  = -CUDART_INF_F;
        cn[r] = 0;
    }

    int cur = 0;          // stage holding chunk i
    int wr  = 2;          // stage to write chunk i+2 into
    u32 eoff = 64;        // element offset of chunk i+2

    for (int i = 0; i < NCHUNK; i++) {
        CP_WAIT(1);            // chunk i resident
        __syncthreads();       // visible to all; stage 'wr' drained

        // issue chunk i+2 into stage wr
        if (i + 2 < NCHUNK) {
            const u32 bw = sb + (u32)wr * BSZ;
#pragma unroll
            for (int sx = 0; sx < 4; sx++)
                if (sd[sx] != 0xFFFFFFFFu)
                    cp16(bw + sd[sx], gx + so[sx] + eoff);
        }
        CP_COMMIT();
        eoff += 32;

        // MMA chunk i: D[32j x 32t] per warp, 7 ksteps
        float dacc[2][4][4];
#pragma unroll
        for (int mt = 0; mt < 2; mt++)
#pragma unroll
            for (int n = 0; n < 4; n++)
#pragma unroll
                for (int r = 0; r < 4; r++) dacc[mt][n][r] = 0.f;

        const u32 bb = sb + (u32)cur * BSZ + laneBase;
#pragma unroll
        for (int q = 0; q < 7; q++) {
#pragma unroll
            for (int p = 0; p < 2; p++) {
                u32 b0, b1, b2, b3;
                ldsm_x4t(b0, b1, b2, b3, bb + (u32)q * 1024u + xvo[p]);
                mma16816(dacc[0][2 * p],     afr[q][0], b0, b1);
                mma16816(dacc[0][2 * p + 1], afr[q][0], b2, b3);
                mma16816(dacc[1][2 * p],     afr[q][1], b0, b1);
                mma16816(dacc[1][2 * p + 1], afr[q][1], b2, b3);
            }
        }

        // fused epilogue (last chunk: only t 0..7 valid -> ntile 0)
        const int ntmax = (i == NCHUNK - 1) ? 1 : 4;
#pragma unroll
        for (int n = 0; n < 4; n++) {
            if (n < ntmax) {
#pragma unroll
                for (int mt = 0; mt < 2; mt++) {
                    m[2 * mt]     = fmaxf(m[2 * mt],
                                          fmaxf(dacc[mt][n][0], dacc[mt][n][1]));
                    cn[2 * mt]   += (dacc[mt][n][0] > bv[2 * mt])
                                  + (dacc[mt][n][1] > bv[2 * mt]);
                    m[2 * mt + 1] = fmaxf(m[2 * mt + 1],
                                          fmaxf(dacc[mt][n][2], dacc[mt][n][3]));
                    cn[2 * mt + 1] += (dacc[mt][n][2] > bv[2 * mt + 1])
                                    + (dacc[mt][n][3] > bv[2 * mt + 1]);
                }
            }
        }

        cur = (cur == 2) ? 0 : cur + 1;
        wr  = (wr  == 2) ? 0 : wr  + 1;
    }

    // ---- reduce across the 4 lanes of each quad, write out ----
#pragma unroll
    for (int o = 1; o < 4; o <<= 1) {
#pragma unroll
        for (int r = 0; r < 4; r++) {
            m[r]  = fmaxf(m[r], __shfl_xor_sync(0xffffffffu, m[r], o));
            cn[r] += __shfl_xor_sync(0xffffffffu, cn[r], o);
        }
    }
    if ((lane & 3) == 0) {
        float* ob = out + (size_t)b * 20000 + di * 2000;
#pragma unroll
        for (int r = 0; r < 4; r++) {
            if (jr[r] < 1000) {
                ob[jr[r]]        = m[r];
                ob[1000 + jr[r]] = (float)cn[r] * (1.0f / LSEQ);
            }
        }
    }
}

extern "C" void kernel_launch(void* const* d_in, const int* in_sizes, int n_in,
                              void* d_out, int out_size)
{
    const float* x    = (const float*)d_in[0];  // [16,12,5000]
    const float* W    = (const float*)d_in[1];  // [10,1000,12,9]
    const float* bias = (const float*)d_in[2];  // [10,1000]
    float* out = (float*)d_out;                 // [16,20000]

    dim3 pg((ROWLEN / 2 + 255) / 256, NROWS, 8);
    prep_kernel<<<pg, 256>>>(x);

    cudaFuncSetAttribute(mr_hmma, cudaFuncAttributeMaxDynamicSharedMemorySize, SMEMSZ);
    dim3 grid(8, 16, 10);
    mr_hmma<<<grid, 128, SMEMSZ>>>(W, bias, out);
}